// round 1
// baseline (speedup 1.0000x reference)
#include <cuda_runtime.h>

// ---------------------------------------------------------------------------
// Geometry: 4 pyramid levels, voxel counts 32^3, 16^3, 8^3, 4^3.
// Unified buffer layout: [C][37440] where the 37440 positions are the
// concatenation of all levels' voxels (level offsets 0,32768,36864,37376).
// ---------------------------------------------------------------------------
#define TOT 37440

__device__ float g_in36[36 * TOT];   // packed input (36 ch)
__device__ float g_bufA[64 * TOT];   // ping
__device__ float g_bufB[64 * TOT];   // pong
__device__ float g_mean[256];        // [4 levels][64 ch]
__device__ float g_rstd[256];

// ---------------------------------------------------------------------------
// Pack p0..p3 (each [36][S^3]) into unified [36][37440] layout.
// ---------------------------------------------------------------------------
__global__ void pack_kernel(const float* __restrict__ p0, const float* __restrict__ p1,
                            const float* __restrict__ p2, const float* __restrict__ p3,
                            float* __restrict__ out) {
    int c = blockIdx.y;
    int pos = blockIdx.x * 256 + threadIdx.x;
    if (pos >= TOT) return;
    const float* p; int v, voxn;
    if (pos < 32768)      { p = p0; v = pos;         voxn = 32768; }
    else if (pos < 36864) { p = p1; v = pos - 32768; voxn = 4096;  }
    else if (pos < 37376) { p = p2; v = pos - 36864; voxn = 512;   }
    else                  { p = p3; v = pos - 37376; voxn = 64;    }
    out[c * TOT + pos] = p[c * voxn + v];
}

// ---------------------------------------------------------------------------
// Per-(level,channel) mean / rstd for InstanceNorm. 256 blocks, deterministic.
// ---------------------------------------------------------------------------
__global__ void stats_kernel(const float* __restrict__ buf,
                             float* __restrict__ mean, float* __restrict__ rstd) {
    __shared__ float ss[256], sq[256];
    int L = blockIdx.x >> 6, c = blockIdx.x & 63;
    const int voxs[4] = {32768, 4096, 512, 64};
    const int offs[4] = {0, 32768, 36864, 37376};
    int N = voxs[L];
    const float* p = buf + c * TOT + offs[L];
    float s = 0.f, q = 0.f;
    for (int i = threadIdx.x; i < N; i += 256) {
        float x = p[i];
        s += x;
        q = fmaf(x, x, q);
    }
    ss[threadIdx.x] = s; sq[threadIdx.x] = q;
    __syncthreads();
    for (int st = 128; st > 0; st >>= 1) {
        if (threadIdx.x < st) {
            ss[threadIdx.x] += ss[threadIdx.x + st];
            sq[threadIdx.x] += sq[threadIdx.x + st];
        }
        __syncthreads();
    }
    if (threadIdx.x == 0) {
        float m = ss[0] / (float)N;
        float v = sq[0] / (float)N - m * m;
        mean[blockIdx.x] = m;
        rstd[blockIdx.x] = rsqrtf(fmaxf(v, 0.f) + 1e-5f);
    }
}

// ---------------------------------------------------------------------------
// Fused InstanceNorm (affine=False) + PReLU (scalar alpha per layer), in-place.
// ---------------------------------------------------------------------------
__global__ void np_kernel(float* __restrict__ buf, const float* __restrict__ mean,
                          const float* __restrict__ rstd, const float* __restrict__ a,
                          int aidx) {
    int c = blockIdx.y;
    int pos = blockIdx.x * 256 + threadIdx.x;
    if (pos >= TOT) return;
    int L = (pos >= 32768) + (pos >= 36864) + (pos >= 37376);
    float alpha = __ldg(a + aidx);
    int idx = c * TOT + pos;
    float x = (buf[idx] - mean[(L << 6) + c]) * rstd[(L << 6) + c];
    buf[idx] = x >= 0.f ? x : alpha * x;
}

// ---------------------------------------------------------------------------
// Unified 3x3x3 SAME conv over all 4 levels in one grid.
// Block = 128 threads; each active thread computes 4 consecutive W voxels
// x OCW output channels. Per-level tile geometry makes per-block work equal:
//   L0 (32^3): 64 spatial tiles of (2,8,32)
//   L1 (16^3):  8 spatial tiles of (4,8,16)
//   L2 ( 8^3):  1 tile (8,8,8)
//   L3 ( 4^3):  1 tile (4,4,4) (16 active threads, same per-thread work)
// grid.x = n_oc_groups * 74.
// FINAL=true: write channels-last into d_out at head_base, Cout=COUT.
// FINAL=false: write [oc][TOT] with bias (Cout=64).
// ---------------------------------------------------------------------------
template <int OCW, bool FINAL>
__global__ void __launch_bounds__(128) conv3d_kernel(
    const float* __restrict__ in, const float* __restrict__ wgt,
    const float* __restrict__ bias, float* __restrict__ out,
    int CIN, int COUT, int head_base) {
    __shared__ float in_s[1400];        // max tile 4*10*35 (padded rows)
    __shared__ float w_s[OCW * 27];

    const int t = threadIdx.x;
    const int ocg = blockIdx.x / 74;
    const int r = blockIdx.x - ocg * 74;

    int L, sp;
    if (r < 64)      { L = 0; sp = r; }
    else if (r < 72) { L = 1; sp = r - 64; }
    else if (r == 72){ L = 2; sp = 0; }
    else             { L = 3; sp = 0; }

    int S, off, cumvox, d0, h0, tz, ty, tx, ZT, YT, XT, XP;
    bool active = true;
    switch (L) {
      case 0: S = 32; off = 0;     cumvox = 0;
              d0 = (sp >> 2) * 2; h0 = (sp & 3) * 8;
              tx = t & 7; ty = (t >> 3) & 7; tz = t >> 6;
              ZT = 4;  YT = 10; XT = 34; XP = 35; break;
      case 1: S = 16; off = 32768; cumvox = 32768;
              d0 = (sp >> 1) * 4; h0 = (sp & 1) * 8;
              tx = t & 3; ty = (t >> 2) & 7; tz = t >> 5;
              ZT = 6;  YT = 10; XT = 18; XP = 19; break;
      case 2: S = 8;  off = 36864; cumvox = 36864;
              d0 = 0; h0 = 0;
              tx = t & 1; ty = (t >> 1) & 7; tz = t >> 4;
              ZT = 10; YT = 10; XT = 10; XP = 11; break;
      default:S = 4;  off = 37376; cumvox = 37376;
              d0 = 0; h0 = 0;
              tx = 0; ty = t & 3; tz = (t >> 2) & 3;
              ZT = 6;  YT = 6;  XT = 6;  XP = 7;
              active = (t < 16); break;
    }

    float acc[OCW][4];
#pragma unroll
    for (int j = 0; j < OCW; ++j) {
        acc[j][0] = 0.f; acc[j][1] = 0.f; acc[j][2] = 0.f; acc[j][3] = 0.f;
    }

    const int lane = t & 31, wrp = t >> 5;

    for (int ic = 0; ic < CIN; ++ic) {
        // ---- cooperative input tile load (zero-padded SAME halo) ----
        const float* src_ic = in + ic * TOT + off;
        for (int z = 0; z < ZT; ++z) {
            int gz = d0 - 1 + z;
            bool zok = (unsigned)gz < (unsigned)S;
            for (int y = wrp; y < YT; y += 4) {
                int gy = h0 - 1 + y;
                bool ok = zok && ((unsigned)gy < (unsigned)S);
                const float* srow = src_ic + (gz * S + gy) * S;
                float* drow = &in_s[(z * YT + y) * XP];
                for (int x = lane; x < XT; x += 32) {
                    int gx = x - 1;
                    drow[x] = (ok && (unsigned)gx < (unsigned)S) ? srow[gx] : 0.f;
                }
            }
        }
        // ---- weight slice load ----
        for (int i = t; i < OCW * 27; i += 128) {
            int j = i / 27, k = i - j * 27;
            int oc = ocg * OCW + j;
            w_s[i] = (oc < COUT) ? wgt[(oc * CIN + ic) * 27 + k] : 0.f;
        }
        __syncthreads();

        if (active) {
#pragma unroll
            for (int kz = 0; kz < 3; ++kz) {
#pragma unroll
                for (int ky = 0; ky < 3; ++ky) {
                    const float* ip = &in_s[((tz + kz) * YT + (ty + ky)) * XP + (tx << 2)];
                    float x0 = ip[0], x1 = ip[1], x2 = ip[2];
                    float x3 = ip[3], x4 = ip[4], x5 = ip[5];
                    const float* wr = &w_s[(kz * 3 + ky) * 3];
#pragma unroll
                    for (int j = 0; j < OCW; ++j) {
                        float w0 = wr[j * 27 + 0];
                        float w1 = wr[j * 27 + 1];
                        float w2 = wr[j * 27 + 2];
                        acc[j][0] = fmaf(x0, w0, acc[j][0]);
                        acc[j][1] = fmaf(x1, w0, acc[j][1]);
                        acc[j][2] = fmaf(x2, w0, acc[j][2]);
                        acc[j][3] = fmaf(x3, w0, acc[j][3]);
                        acc[j][0] = fmaf(x1, w1, acc[j][0]);
                        acc[j][1] = fmaf(x2, w1, acc[j][1]);
                        acc[j][2] = fmaf(x3, w1, acc[j][2]);
                        acc[j][3] = fmaf(x4, w1, acc[j][3]);
                        acc[j][0] = fmaf(x2, w2, acc[j][0]);
                        acc[j][1] = fmaf(x3, w2, acc[j][1]);
                        acc[j][2] = fmaf(x4, w2, acc[j][2]);
                        acc[j][3] = fmaf(x5, w2, acc[j][3]);
                    }
                }
            }
        }
        __syncthreads();
    }

    if (!active) return;
    int d = d0 + tz, h = h0 + ty, w0i = tx << 2;
    int vidx = (d * S + h) * S + w0i;
#pragma unroll
    for (int j = 0; j < OCW; ++j) {
        int oc = ocg * OCW + j;
        if (oc >= COUT) break;
        float b = bias[oc];
        if (FINAL) {
            int base = head_base + (cumvox + vidx) * COUT + oc;
            out[base + 0 * COUT] = acc[j][0] + b;
            out[base + 1 * COUT] = acc[j][1] + b;
            out[base + 2 * COUT] = acc[j][2] + b;
            out[base + 3 * COUT] = acc[j][3] + b;
        } else {
            float* o = out + oc * TOT + off + vidx;
            o[0] = acc[j][0] + b;
            o[1] = acc[j][1] + b;
            o[2] = acc[j][2] + b;
            o[3] = acc[j][3] + b;
        }
    }
}

// ---------------------------------------------------------------------------
// Host launcher: 1 pack + per head (4 conv + 4 stats + 4 norm-prelu + final).
// All on the default stream; graph-capturable; no allocations.
// ---------------------------------------------------------------------------
extern "C" void kernel_launch(void* const* d_in, const int* in_sizes, int n_in,
                              void* d_out, int out_size) {
    (void)in_sizes; (void)n_in; (void)out_size;

    const float* p0 = (const float*)d_in[0];
    const float* p1 = (const float*)d_in[1];
    const float* p2 = (const float*)d_in[2];
    const float* p3 = (const float*)d_in[3];

    float *in36, *bufA, *bufB, *mean, *rstd;
    cudaGetSymbolAddress((void**)&in36, g_in36);
    cudaGetSymbolAddress((void**)&bufA, g_bufA);
    cudaGetSymbolAddress((void**)&bufB, g_bufB);
    cudaGetSymbolAddress((void**)&mean, g_mean);
    cudaGetSymbolAddress((void**)&rstd, g_rstd);

    float* out = (float*)d_out;

    // pack inputs once (shared by both heads)
    pack_kernel<<<dim3(147, 36), 256>>>(p0, p1, p2, p3, in36);

    const int CLS_TOTAL = TOT * 18;  // 673920: reg head output starts here

    for (int head = 0; head < 2; ++head) {
        int base = 4 + head * 7;
        const float* w1   = (const float*)d_in[base + 0];
        const float* b1   = (const float*)d_in[base + 1];
        const float* w234 = (const float*)d_in[base + 2];
        const float* b234 = (const float*)d_in[base + 3];
        const float* aP   = (const float*)d_in[base + 4];
        const float* wf   = (const float*)d_in[base + 5];
        const float* bf   = (const float*)d_in[base + 6];

        // conv1: 36 -> 64
        conv3d_kernel<16, false><<<4 * 74, 128>>>(in36, w1, b1, bufA, 36, 64, 0);
        stats_kernel<<<256, 256>>>(bufA, mean, rstd);
        np_kernel<<<dim3(147, 64), 256>>>(bufA, mean, rstd, aP, 0);

        // conv2..4: 64 -> 64, ping-pong A<->B
        float* src = bufA; float* dst = bufB;
        for (int i = 0; i < 3; ++i) {
            conv3d_kernel<16, false><<<4 * 74, 128>>>(
                src, w234 + (size_t)i * 64 * 64 * 27, b234 + i * 64, dst, 64, 64, 0);
            stats_kernel<<<256, 256>>>(dst, mean, rstd);
            np_kernel<<<dim3(147, 64), 256>>>(dst, mean, rstd, aP, i + 1);
            float* tmp = src; src = dst; dst = tmp;
        }
        // after 3 iterations, normalized activations live in `src`

        // final conv, channels-last directly into d_out
        if (head == 0) {
            conv3d_kernel<6, true><<<3 * 74, 128>>>(src, wf, bf, out, 64, 18, 0);
        } else {
            conv3d_kernel<6, true><<<9 * 74, 128>>>(src, wf, bf, out, 64, 54, CLS_TOTAL);
        }
    }
}

// round 2
// speedup vs baseline: 1.7993x; 1.7993x over previous
#include <cuda_runtime.h>

#define TOT 37440

__device__ float g_in36[36 * TOT];
__device__ float g_bufA[64 * TOT];
__device__ float g_bufB[64 * TOT];
__device__ float g_mean[256];   // [4 levels][64 ch]
__device__ float g_rstd[256];

// ---------------------------------------------------------------------------
// Pack p0..p3 (each [36][S^3]) into unified [36][37440] layout.
// ---------------------------------------------------------------------------
__global__ void pack_kernel(const float* __restrict__ p0, const float* __restrict__ p1,
                            const float* __restrict__ p2, const float* __restrict__ p3,
                            float* __restrict__ out) {
    int c = blockIdx.y;
    int pos = blockIdx.x * 256 + threadIdx.x;
    if (pos >= TOT) return;
    const float* p; int v, voxn;
    if (pos < 32768)      { p = p0; v = pos;         voxn = 32768; }
    else if (pos < 36864) { p = p1; v = pos - 32768; voxn = 4096;  }
    else if (pos < 37376) { p = p2; v = pos - 36864; voxn = 512;   }
    else                  { p = p3; v = pos - 37376; voxn = 64;    }
    out[c * TOT + pos] = p[c * voxn + v];
}

// ---------------------------------------------------------------------------
// Per-(level,channel) mean / rstd for InstanceNorm. 256 blocks, deterministic.
// ---------------------------------------------------------------------------
__global__ void stats_kernel(const float* __restrict__ buf,
                             float* __restrict__ mean, float* __restrict__ rstd) {
    __shared__ float ss[256], sq[256];
    int L = blockIdx.x >> 6, c = blockIdx.x & 63;
    const int voxs[4] = {32768, 4096, 512, 64};
    const int offs[4] = {0, 32768, 36864, 37376};
    int N = voxs[L];
    const float* p = buf + c * TOT + offs[L];
    float s = 0.f, q = 0.f;
    for (int i = threadIdx.x; i < N; i += 256) {
        float x = p[i];
        s += x;
        q = fmaf(x, x, q);
    }
    ss[threadIdx.x] = s; sq[threadIdx.x] = q;
    __syncthreads();
    for (int st = 128; st > 0; st >>= 1) {
        if (threadIdx.x < st) {
            ss[threadIdx.x] += ss[threadIdx.x + st];
            sq[threadIdx.x] += sq[threadIdx.x + st];
        }
        __syncthreads();
    }
    if (threadIdx.x == 0) {
        float m = ss[0] / (float)N;
        float v = sq[0] / (float)N - m * m;
        mean[blockIdx.x] = m;
        rstd[blockIdx.x] = rsqrtf(fmaxf(v, 0.f) + 1e-5f);
    }
}

// ---------------------------------------------------------------------------
// Compile-time level geometry.
// ---------------------------------------------------------------------------
template <int LEV> struct Geo;
template <> struct Geo<0> { enum { S = 32, OFF = 0,     ZT = 4,  YT = 10, XT = 34, XP = 35 }; };
template <> struct Geo<1> { enum { S = 16, OFF = 32768, ZT = 6,  YT = 10, XT = 18, XP = 19 }; };
template <> struct Geo<2> { enum { S = 8,  OFF = 36864, ZT = 10, YT = 10, XT = 10, XP = 11 }; };
template <> struct Geo<3> { enum { S = 4,  OFF = 37376, ZT = 6,  YT = 6,  XT = 6,  XP = 7  }; };

// ---------------------------------------------------------------------------
// Per-level conv body. 128 threads; active thread computes 4 consecutive W
// voxels x OCW output channels. Double-buffered smem, one barrier per ic.
// NORM: apply (x-mean)*rstd then PReLU while loading input tile (zero halo
// stays zero, matching SAME-padding-after-norm).
// ---------------------------------------------------------------------------
template <int LEV, int OCW, bool FINAL, bool NORM>
__device__ __forceinline__ void conv_body(
    int sp, int ocg,
    const float* __restrict__ in, const float* __restrict__ wgt,
    const float* __restrict__ bias, float* __restrict__ out,
    const float* __restrict__ mean, const float* __restrict__ rstd,
    float alpha, int CIN, int COUT, int head_base,
    float* __restrict__ in_s, float* __restrict__ w_s) {

    typedef Geo<LEV> G;
    constexpr int S  = G::S,  OFF = G::OFF;
    constexpr int ZT = G::ZT, YT = G::YT, XT = G::XT, XP = G::XP;
    constexpr int TILE = ZT * YT * XP;   // smem buffer stride
    constexpr int TOTE = ZT * YT * XT;   // loaded elements per buffer
    constexpr int WSL  = OCW * 27;

    const int t = threadIdx.x;
    int tz, ty, tx, d0 = 0, h0 = 0;
    bool active = true;
    if (LEV == 0) { tx = t & 7; ty = (t >> 3) & 7; tz = t >> 6;
                    d0 = (sp >> 2) * 2; h0 = (sp & 3) * 8; }
    else if (LEV == 1) { tx = t & 3; ty = (t >> 2) & 7; tz = t >> 5;
                    d0 = (sp >> 1) * 4; h0 = (sp & 1) * 8; }
    else if (LEV == 2) { tx = t & 1; ty = (t >> 1) & 7; tz = t >> 4; }
    else { tx = 0; ty = t & 3; tz = (t >> 2) & 3; active = (t < 16); }

    float acc[OCW][4];
#pragma unroll
    for (int j = 0; j < OCW; ++j) {
        acc[j][0] = 0.f; acc[j][1] = 0.f; acc[j][2] = 0.f; acc[j][3] = 0.f;
    }

    // tile + weight loaders (cooperative, all 128 threads)
    auto load_tile = [&](int b, int ic) {
        float m = 0.f, r = 0.f;
        if (NORM) { m = mean[LEV * 64 + ic]; r = rstd[LEV * 64 + ic]; }
        const float* src = in + ic * TOT + OFF;
        float* dst = in_s + b * TILE;
#pragma unroll
        for (int i = 0; i < (TOTE + 127) / 128; ++i) {
            int idx = i * 128 + t;
            if ((TOTE % 128 == 0) || idx < TOTE) {
                int z = idx / (YT * XT), rem = idx - z * (YT * XT);
                int y = rem / XT, x = rem - y * XT;
                int gz = d0 - 1 + z, gy = h0 - 1 + y, gx = x - 1;
                float v = 0.f;
                if ((unsigned)gz < (unsigned)S && (unsigned)gy < (unsigned)S &&
                    (unsigned)gx < (unsigned)S) {
                    v = src[(gz * S + gy) * S + gx];
                    if (NORM) {
                        v = (v - m) * r;
                        v = v >= 0.f ? v : alpha * v;
                    }
                }
                dst[(z * YT + y) * XP + x] = v;
            }
        }
    };
    auto load_w = [&](int b, int ic) {
#pragma unroll
        for (int i = t; i < WSL; i += 128) {
            int j = i / 27, k = i - j * 27;
            int oc = ocg * OCW + j;
            w_s[b * WSL + i] = (oc < COUT) ? wgt[(oc * CIN + ic) * 27 + k] : 0.f;
        }
    };

    load_tile(0, 0);
    load_w(0, 0);

    for (int ic = 0; ic < CIN; ++ic) {
        __syncthreads();
        int cur = ic & 1, nb = cur ^ 1;
        if (ic + 1 < CIN) { load_tile(nb, ic + 1); load_w(nb, ic + 1); }

        if (active) {
            const float* buf = in_s + cur * TILE;
            const float* wb  = w_s + cur * WSL;
#pragma unroll
            for (int kz = 0; kz < 3; ++kz) {
#pragma unroll
                for (int ky = 0; ky < 3; ++ky) {
                    const float* ip = &buf[((tz + kz) * YT + (ty + ky)) * XP + (tx << 2)];
                    float x0 = ip[0], x1 = ip[1], x2 = ip[2];
                    float x3 = ip[3], x4 = ip[4], x5 = ip[5];
                    const float* wr = &wb[(kz * 3 + ky) * 3];
#pragma unroll
                    for (int j = 0; j < OCW; ++j) {
                        float w0 = wr[j * 27 + 0];
                        float w1 = wr[j * 27 + 1];
                        float w2 = wr[j * 27 + 2];
                        acc[j][0] = fmaf(x0, w0, acc[j][0]);
                        acc[j][1] = fmaf(x1, w0, acc[j][1]);
                        acc[j][2] = fmaf(x2, w0, acc[j][2]);
                        acc[j][3] = fmaf(x3, w0, acc[j][3]);
                        acc[j][0] = fmaf(x1, w1, acc[j][0]);
                        acc[j][1] = fmaf(x2, w1, acc[j][1]);
                        acc[j][2] = fmaf(x3, w1, acc[j][2]);
                        acc[j][3] = fmaf(x4, w1, acc[j][3]);
                        acc[j][0] = fmaf(x2, w2, acc[j][0]);
                        acc[j][1] = fmaf(x3, w2, acc[j][1]);
                        acc[j][2] = fmaf(x4, w2, acc[j][2]);
                        acc[j][3] = fmaf(x5, w2, acc[j][3]);
                    }
                }
            }
        }
    }

    if (!active) return;
    int d = d0 + tz, h = h0 + ty, w0i = tx << 2;
    int vidx = (d * S + h) * S + w0i;
#pragma unroll
    for (int j = 0; j < OCW; ++j) {
        int oc = ocg * OCW + j;
        if (oc >= COUT) break;
        float b = bias[oc];
        if (FINAL) {
            int base = head_base + (OFF + vidx) * COUT + oc;
            out[base + 0 * COUT] = acc[j][0] + b;
            out[base + 1 * COUT] = acc[j][1] + b;
            out[base + 2 * COUT] = acc[j][2] + b;
            out[base + 3 * COUT] = acc[j][3] + b;
        } else {
            float* o = out + oc * TOT + OFF + vidx;
            o[0] = acc[j][0] + b;
            o[1] = acc[j][1] + b;
            o[2] = acc[j][2] + b;
            o[3] = acc[j][3] + b;
        }
    }
}

// ---------------------------------------------------------------------------
// Unified conv kernel: grid.x = n_oc_groups * 74.
//   r<64: L0 (64 tiles of 2x8x32); r<72: L1 (8 tiles of 4x8x16);
//   r==72: L2; r==73: L3.
// ---------------------------------------------------------------------------
template <int OCW, bool FINAL, bool NORM>
__global__ void __launch_bounds__(128) conv_kernel(
    const float* __restrict__ in, const float* __restrict__ wgt,
    const float* __restrict__ bias, float* __restrict__ out,
    const float* __restrict__ mean, const float* __restrict__ rstd,
    const float* __restrict__ aP, int aidx,
    int CIN, int COUT, int head_base) {
    __shared__ float in_s[2 * 1400];
    __shared__ float w_s[2 * OCW * 27];

    int ocg = blockIdx.x / 74;
    int r = blockIdx.x - ocg * 74;
    float alpha = NORM ? __ldg(aP + aidx) : 0.f;

    if (r < 64)
        conv_body<0, OCW, FINAL, NORM>(r, ocg, in, wgt, bias, out, mean, rstd,
                                       alpha, CIN, COUT, head_base, in_s, w_s);
    else if (r < 72)
        conv_body<1, OCW, FINAL, NORM>(r - 64, ocg, in, wgt, bias, out, mean, rstd,
                                       alpha, CIN, COUT, head_base, in_s, w_s);
    else if (r == 72)
        conv_body<2, OCW, FINAL, NORM>(0, ocg, in, wgt, bias, out, mean, rstd,
                                       alpha, CIN, COUT, head_base, in_s, w_s);
    else
        conv_body<3, OCW, FINAL, NORM>(0, ocg, in, wgt, bias, out, mean, rstd,
                                       alpha, CIN, COUT, head_base, in_s, w_s);
}

// ---------------------------------------------------------------------------
// Host launcher: pack + per head (conv1, [stats, conv_norm]x3, stats, final).
// Norm+PReLU fused into consumer conv's tile load. 19 launches total.
// ---------------------------------------------------------------------------
extern "C" void kernel_launch(void* const* d_in, const int* in_sizes, int n_in,
                              void* d_out, int out_size) {
    (void)in_sizes; (void)n_in; (void)out_size;

    const float* p0 = (const float*)d_in[0];
    const float* p1 = (const float*)d_in[1];
    const float* p2 = (const float*)d_in[2];
    const float* p3 = (const float*)d_in[3];

    float *in36, *bufA, *bufB, *mean, *rstd;
    cudaGetSymbolAddress((void**)&in36, g_in36);
    cudaGetSymbolAddress((void**)&bufA, g_bufA);
    cudaGetSymbolAddress((void**)&bufB, g_bufB);
    cudaGetSymbolAddress((void**)&mean, g_mean);
    cudaGetSymbolAddress((void**)&rstd, g_rstd);

    float* out = (float*)d_out;

    pack_kernel<<<dim3(147, 36), 256>>>(p0, p1, p2, p3, in36);

    const int CLS_TOTAL = TOT * 18;

    for (int head = 0; head < 2; ++head) {
        int base = 4 + head * 7;
        const float* w1   = (const float*)d_in[base + 0];
        const float* b1   = (const float*)d_in[base + 1];
        const float* w234 = (const float*)d_in[base + 2];
        const float* b234 = (const float*)d_in[base + 3];
        const float* aP   = (const float*)d_in[base + 4];
        const float* wf   = (const float*)d_in[base + 5];
        const float* bf   = (const float*)d_in[base + 6];

        // conv1: 36 -> 64 (raw input, no norm), out -> bufA (raw)
        conv_kernel<8, false, false><<<8 * 74, 128>>>(
            in36, w1, b1, bufA, mean, rstd, aP, 0, 36, 64, 0);
        stats_kernel<<<256, 256>>>(bufA, mean, rstd);

        // conv2..4: 64 -> 64, norm(prev)+prelu fused on load, ping-pong
        float* src = bufA; float* dst = bufB;
        for (int i = 0; i < 3; ++i) {
            conv_kernel<8, false, true><<<8 * 74, 128>>>(
                src, w234 + (size_t)i * 64 * 64 * 27, b234 + i * 64, dst,
                mean, rstd, aP, i, 64, 64, 0);
            stats_kernel<<<256, 256>>>(dst, mean, rstd);
            float* tmp = src; src = dst; dst = tmp;
        }
        // normalized-on-load source for final conv is `src` (raw conv4 out)

        if (head == 0) {
            conv_kernel<6, true, true><<<3 * 74, 128>>>(
                src, wf, bf, out, mean, rstd, aP, 3, 64, 18, 0);
        } else {
            conv_kernel<6, true, true><<<9 * 74, 128>>>(
                src, wf, bf, out, mean, rstd, aP, 3, 64, 54, CLS_TOTAL);
        }
    }
}